// round 6
// baseline (speedup 1.0000x reference)
#include <cuda_runtime.h>
#include <math.h>

// ---------------------------------------------------------------------------
// VQ-VAE 3D forward:
//   enc: conv(1->16,k4s2p1)+relu -> conv(16->32)+relu -> conv(32->64) = z_e
//   vq : nearest codebook entry (512x64), quantized = codebook[argmin]
//   dec: convT(64->32)+relu -> convT(32->16)+relu -> convT(16->1)+sigmoid
// Output layout in d_out (float): [x_hat (4*1*128^3) | quantized (4*64*16^3) | z_e (4*64*16^3)]
// ---------------------------------------------------------------------------

// scratch (no allocations allowed) -- reused across stages
__device__ float g_h1[4 * 16 * 64 * 64 * 64]; // conv1 out / dec2 out (64 MB)
__device__ float g_h2[4 * 32 * 32 * 32 * 32]; // conv2 out / dec1 out (16 MB)

// ===========================================================================
// Strided conv3d, k=4 s=2 p=1. One thread = one spatial output position,
// COVEC output channels in registers. Weights for the co-group in SMEM.
// ACT: 0 none, 1 relu
// ===========================================================================
template <int CIN, int COVEC, int ACT>
__global__ void conv_s2_kernel(const float* __restrict__ x,
                               const float* __restrict__ w,   // [Cout][CIN][4][4][4]
                               const float* __restrict__ bias,
                               float* __restrict__ y,
                               int Din, int Dout, int Cout)
{
    extern __shared__ float ws[]; // [CIN*64][COVEC]
    const int co0 = blockIdx.y * COVEC;
    const int n   = blockIdx.z;

    const int WTOT = CIN * 64 * COVEC;
    for (int e = threadIdx.x; e < WTOT; e += blockDim.x) {
        int v  = e % COVEC;
        int r  = e / COVEC;          // ci*64 + t
        int ci = r >> 6, t = r & 63;
        ws[e] = w[((co0 + v) * CIN + ci) * 64 + t];
    }
    __syncthreads();

    const int pos = blockIdx.x * blockDim.x + threadIdx.x; // spatial sizes are multiples of 256
    const int ow = pos % Dout;
    const int oh = (pos / Dout) % Dout;
    const int od = pos / (Dout * Dout);

    int iz[4], iy[4], ix[4];
    bool vz[4], vy[4], vx[4];
#pragma unroll
    for (int t = 0; t < 4; t++) {
        iz[t] = 2 * od - 1 + t; vz[t] = (unsigned)iz[t] < (unsigned)Din;
        iy[t] = 2 * oh - 1 + t; vy[t] = (unsigned)iy[t] < (unsigned)Din;
        ix[t] = 2 * ow - 1 + t; vx[t] = (unsigned)ix[t] < (unsigned)Din;
    }

    float acc[COVEC];
#pragma unroll
    for (int v = 0; v < COVEC; v++) acc[v] = bias[co0 + v];

    const int DIN2 = Din * Din;
    const float* xn = x + (size_t)n * CIN * Din * DIN2;

    for (int ci = 0; ci < CIN; ci++) {
        const float* xc = xn + (size_t)ci * Din * DIN2;
        const float* wc = ws + ci * 64 * COVEC;
#pragma unroll
        for (int a = 0; a < 4; a++) {
#pragma unroll
            for (int b = 0; b < 4; b++) {
                const float* row = xc + iz[a] * DIN2 + iy[b] * Din;
                const bool vab = vz[a] && vy[b];
                const float* wk = wc + ((a * 4 + b) * 4) * COVEC;
#pragma unroll
                for (int c = 0; c < 4; c++) {
                    float xv = (vab && vx[c]) ? __ldg(row + ix[c]) : 0.f;
                    const float* wv = wk + c * COVEC;
#pragma unroll
                    for (int v = 0; v < COVEC; v++)
                        acc[v] = fmaf(xv, wv[v], acc[v]);
                }
            }
        }
    }

    const int OUT3 = Dout * Dout * Dout;
    float* yo = y + ((size_t)n * Cout + co0) * OUT3 + pos;
#pragma unroll
    for (int v = 0; v < COVEC; v++) {
        float r = acc[v];
        if (ACT == 1) r = fmaxf(r, 0.f);
        yo[(size_t)v * OUT3] = r;
    }
}

// ===========================================================================
// Transposed conv3d, k=4 s=2 p=1 (output = 2*input per dim).
// For output index o (per dim) the contributing (input,tap) pairs are:
//   i0 = (o+1)>>1, t0 = o+1-2*i0   and   i1 = i0-1, t1 = t0+2
// ACT: 0 none, 1 relu, 2 sigmoid
// Weights: PyTorch ConvTranspose layout [CIN][Cout][4][4][4].
// ===========================================================================
template <int CIN, int COVEC, int ACT>
__global__ void convT_s2_kernel(const float* __restrict__ x,
                                const float* __restrict__ w,
                                const float* __restrict__ bias,
                                float* __restrict__ y,
                                int In, int Out, int Cout)
{
    extern __shared__ float ws[]; // [CIN*64][COVEC]
    const int co0 = blockIdx.y * COVEC;
    const int n   = blockIdx.z;

    const int WTOT = CIN * 64 * COVEC;
    for (int e = threadIdx.x; e < WTOT; e += blockDim.x) {
        int v  = e % COVEC;
        int r  = e / COVEC;
        int ci = r >> 6, t = r & 63;
        ws[e] = w[((size_t)ci * Cout + co0 + v) * 64 + t];
    }
    __syncthreads();

    const int pos = blockIdx.x * blockDim.x + threadIdx.x;
    const int ow = pos % Out;
    const int oh = (pos / Out) % Out;
    const int od = pos / (Out * Out);

    int id_[2], td_[2]; bool vd_[2];
    int ih_[2], th_[2]; bool vh_[2];
    int iw_[2], tw_[2]; bool vw_[2];
    {
        int i0 = (od + 1) >> 1; td_[0] = od + 1 - 2 * i0; id_[0] = i0; vd_[0] = (i0 < In);
        id_[1] = i0 - 1; td_[1] = td_[0] + 2; vd_[1] = (i0 - 1 >= 0);
        i0 = (oh + 1) >> 1; th_[0] = oh + 1 - 2 * i0; ih_[0] = i0; vh_[0] = (i0 < In);
        ih_[1] = i0 - 1; th_[1] = th_[0] + 2; vh_[1] = (i0 - 1 >= 0);
        i0 = (ow + 1) >> 1; tw_[0] = ow + 1 - 2 * i0; iw_[0] = i0; vw_[0] = (i0 < In);
        iw_[1] = i0 - 1; tw_[1] = tw_[0] + 2; vw_[1] = (i0 - 1 >= 0);
    }

    int xoff[8], koff[8]; bool vv[8];
    int q = 0;
#pragma unroll
    for (int a = 0; a < 2; a++)
#pragma unroll
        for (int b = 0; b < 2; b++)
#pragma unroll
            for (int c = 0; c < 2; c++) {
                vv[q] = vd_[a] && vh_[b] && vw_[c];
                int zi = vd_[a] ? id_[a] : 0;
                int yi = vh_[b] ? ih_[b] : 0;
                int xi = vw_[c] ? iw_[c] : 0;
                xoff[q] = (zi * In + yi) * In + xi;
                koff[q] = ((td_[a] * 4 + th_[b]) * 4 + tw_[c]) * COVEC;
                q++;
            }

    float acc[COVEC];
#pragma unroll
    for (int v = 0; v < COVEC; v++) acc[v] = bias[co0 + v];

    const int IN3 = In * In * In;
    const float* xn = x + (size_t)n * CIN * IN3;

    for (int ci = 0; ci < CIN; ci++) {
        const float* xc = xn + (size_t)ci * IN3;
        const float* wc = ws + ci * 64 * COVEC;
#pragma unroll
        for (int j = 0; j < 8; j++) {
            float xv = vv[j] ? __ldg(xc + xoff[j]) : 0.f;
            const float* wv = wc + koff[j];
#pragma unroll
            for (int v = 0; v < COVEC; v++)
                acc[v] = fmaf(xv, wv[v], acc[v]);
        }
    }

    const int OUT3 = Out * Out * Out;
    float* yo = y + ((size_t)n * Cout + co0) * OUT3 + pos;
#pragma unroll
    for (int v = 0; v < COVEC; v++) {
        float r = acc[v];
        if (ACT == 1) r = fmaxf(r, 0.f);
        if (ACT == 2) r = 1.f / (1.f + __expf(-r));
        yo[(size_t)v * OUT3] = r;
    }
}

// ===========================================================================
// Vector quantization: for each of 4*4096 positions, argmin_k ||z - c_k||^2.
// ||z||^2 is constant per position -> score = ||c_k||^2 - 2 z.c_k.
// Codebook (512x64 = 128 KB) + norms in dynamic SMEM; z in 64 registers.
// Ascending k with strict '<' matches jnp.argmin first-occurrence tie-break.
// ===========================================================================
__global__ void vq_kernel(const float* __restrict__ ze,
                          const float* __restrict__ cb,
                          float* __restrict__ quant)
{
    extern __shared__ float s[];
    float* scb   = s;            // [512*64]
    float* snorm = s + 512 * 64; // [512]

    for (int e = threadIdx.x; e < 512 * 64; e += blockDim.x) scb[e] = cb[e];
    __syncthreads();
    for (int k = threadIdx.x; k < 512; k += blockDim.x) {
        float a = 0.f;
#pragma unroll
        for (int j = 0; j < 64; j++) { float c = scb[k * 64 + j]; a = fmaf(c, c, a); }
        snorm[k] = a;
    }
    __syncthreads();

    const int p  = blockIdx.x * blockDim.x + threadIdx.x; // 0..16383
    const int n  = p >> 12;
    const int sp = p & 4095;

    const float* zp = ze + (size_t)(n * 64) * 4096 + sp;
    float z[64];
#pragma unroll
    for (int j = 0; j < 64; j++) z[j] = __ldg(zp + j * 4096);

    float best = 3.4e38f;
    int   bi   = 0;
    for (int k = 0; k < 512; k++) {
        const float4* c4 = (const float4*)(scb + k * 64);
        float d0 = 0.f, d1 = 0.f, d2 = 0.f, d3 = 0.f;
#pragma unroll
        for (int j = 0; j < 16; j++) {
            float4 cc = c4[j];
            d0 = fmaf(z[4 * j + 0], cc.x, d0);
            d1 = fmaf(z[4 * j + 1], cc.y, d1);
            d2 = fmaf(z[4 * j + 2], cc.z, d2);
            d3 = fmaf(z[4 * j + 3], cc.w, d3);
        }
        float score = snorm[k] - 2.f * ((d0 + d1) + (d2 + d3));
        if (score < best) { best = score; bi = k; }
    }

    float* qp = quant + (size_t)(n * 64) * 4096 + sp;
#pragma unroll
    for (int j = 0; j < 64; j++) qp[j * 4096] = scb[bi * 64 + j];
}

// ===========================================================================
// Launch
// ===========================================================================
extern "C" void kernel_launch(void* const* d_in, const int* in_sizes, int n_in,
                              void* d_out, int out_size)
{
    const float* x   = (const float*)d_in[0];
    const float* w1  = (const float*)d_in[1];
    const float* b1  = (const float*)d_in[2];
    const float* w2  = (const float*)d_in[3];
    const float* b2  = (const float*)d_in[4];
    const float* w3  = (const float*)d_in[5];
    const float* b3  = (const float*)d_in[6];
    const float* cb  = (const float*)d_in[7];
    const float* dw1 = (const float*)d_in[8];
    const float* db1 = (const float*)d_in[9];
    const float* dw2 = (const float*)d_in[10];
    const float* db2 = (const float*)d_in[11];
    const float* dw3 = (const float*)d_in[12];
    const float* db3 = (const float*)d_in[13];

    float* out   = (float*)d_out;
    const int XHAT_N = in_sizes[0];          // 4*1*128^3 = 8388608
    const int Z_N    = 4 * 64 * 16 * 16 * 16; // 1048576
    float* xhat  = out;
    float* quant = out + XHAT_N;
    float* ze    = out + XHAT_N + Z_N;

    float *h1, *h2;
    cudaGetSymbolAddress((void**)&h1, g_h1);
    cudaGetSymbolAddress((void**)&h2, g_h2);

    // opt-in to >48KB dynamic smem (idempotent)
    cudaFuncSetAttribute(conv_s2_kernel<32, 8, 0>,
                         cudaFuncAttributeMaxDynamicSharedMemorySize, 64 * 1024);
    cudaFuncSetAttribute(convT_s2_kernel<64, 4, 1>,
                         cudaFuncAttributeMaxDynamicSharedMemorySize, 64 * 1024);
    cudaFuncSetAttribute(convT_s2_kernel<32, 8, 1>,
                         cudaFuncAttributeMaxDynamicSharedMemorySize, 64 * 1024);
    cudaFuncSetAttribute(vq_kernel,
                         cudaFuncAttributeMaxDynamicSharedMemorySize, (512 * 64 + 512) * 4);

    const int T = 256;

    // enc1: 1->16, 128 -> 64, relu
    {
        dim3 g((64 * 64 * 64) / T, 16 / 16, 4);
        conv_s2_kernel<1, 16, 1><<<g, T, 1 * 64 * 16 * 4>>>(x, w1, b1, h1, 128, 64, 16);
    }
    // enc2: 16->32, 64 -> 32, relu
    {
        dim3 g((32 * 32 * 32) / T, 32 / 8, 4);
        conv_s2_kernel<16, 8, 1><<<g, T, 16 * 64 * 8 * 4>>>(h1, w2, b2, h2, 64, 32, 32);
    }
    // enc3: 32->64, 32 -> 16, no act -> z_e
    {
        dim3 g((16 * 16 * 16) / T, 64 / 8, 4);
        conv_s2_kernel<32, 8, 0><<<g, T, 32 * 64 * 8 * 4>>>(h2, w3, b3, ze, 32, 16, 64);
    }
    // vq: z_e -> quantized
    {
        vq_kernel<<<16384 / 128, 128, (512 * 64 + 512) * 4>>>(ze, cb, quant);
    }
    // dec1: 64->32, 16 -> 32, relu
    {
        dim3 g((32 * 32 * 32) / T, 32 / 4, 4);
        convT_s2_kernel<64, 4, 1><<<g, T, 64 * 64 * 4 * 4>>>(quant, dw1, db1, h2, 16, 32, 32);
    }
    // dec2: 32->16, 32 -> 64, relu
    {
        dim3 g((64 * 64 * 64) / T, 16 / 8, 4);
        convT_s2_kernel<32, 8, 1><<<g, T, 32 * 64 * 8 * 4>>>(h2, dw2, db2, h1, 32, 64, 16);
    }
    // dec3: 16->1, 64 -> 128, sigmoid
    {
        dim3 g((128 * 128 * 128) / T, 1, 4);
        convT_s2_kernel<16, 1, 2><<<g, T, 16 * 64 * 1 * 4>>>(h1, dw3, db3, xhat, 64, 128, 1);
    }
    (void)n_in; (void)out_size;
}

// round 7
// speedup vs baseline: 1.3363x; 1.3363x over previous
#include <cuda_runtime.h>
#include <math.h>

// ---------------------------------------------------------------------------
// VQ-VAE 3D forward:
//   enc: conv(1->16,k4s2p1)+relu -> conv(16->32)+relu -> conv(32->64) = z_e
//   vq : nearest codebook entry (512x64), quantized = codebook[argmin]
//   dec: convT(64->32)+relu -> convT(32->16)+relu -> convT(16->1)+sigmoid
// Output layout in d_out (float): [x_hat (4*1*128^3) | quantized | z_e]
//
// R6: 2x2x2 spatial output blocking on all convs (strided: 6^3 input window,
// transposed: 3^3 input cube, tap->(parity,offset) is bijective), VQ k-split
// across 2 threads/position.
// ---------------------------------------------------------------------------

// scratch (no allocations allowed) -- reused across stages
__device__ float g_h1[4 * 16 * 64 * 64 * 64]; // conv1 out / dec2 out (64 MB)
__device__ float g_h2[4 * 32 * 32 * 32 * 32]; // conv2 out / dec1 out (16 MB)

// ===========================================================================
// Strided conv3d, k=4 s=2 p=1. One thread = 2x2x2 spatial output block x
// COVEC output channels. Input window 6^3 per ci, z-plane cached in regs.
// For output o = 2b + r (per dim): iz = 2o - 1 + a = 4b - 1 + (2r + a).
// So plane index u = 2r + a, u in [0,6); tap a = u - 2r valid iff 0<=a<4.
// ACT: 0 none, 1 relu
// ===========================================================================
template <int CIN, int COVEC, int ACT>
__global__ void conv_s2_blk(const float* __restrict__ x,
                            const float* __restrict__ w,   // [Cout][CIN][4][4][4]
                            const float* __restrict__ bias,
                            float* __restrict__ y,
                            int Din, int Dout, int Cout)
{
    extern __shared__ float ws[]; // [CIN*64][COVEC]
    const int co0 = blockIdx.y * COVEC;
    const int n   = blockIdx.z;

    const int WTOT = CIN * 64 * COVEC;
    for (int e = threadIdx.x; e < WTOT; e += blockDim.x) {
        int v  = e % COVEC;
        int r  = e / COVEC;          // ci*64 + t
        int ci = r >> 6, t = r & 63;
        ws[e] = w[((co0 + v) * CIN + ci) * 64 + t];
    }
    __syncthreads();

    const int B   = Dout >> 1;                            // base grid
    const int pos = blockIdx.x * blockDim.x + threadIdx.x; // base counts are multiples of 256... (>=512)
    const int bw = pos % B;
    const int bh = (pos / B) % B;
    const int bd = pos / (B * B);

    const int zb = 4 * bd - 1, yb = 4 * bh - 1, xb = 4 * bw - 1;
    bool pz[6], py[6], px[6];
#pragma unroll
    for (int u = 0; u < 6; u++) {
        pz[u] = (unsigned)(zb + u) < (unsigned)Din;
        py[u] = (unsigned)(yb + u) < (unsigned)Din;
        px[u] = (unsigned)(xb + u) < (unsigned)Din;
    }

    float acc[8 * COVEC];
#pragma unroll
    for (int o = 0; o < 8; o++)
#pragma unroll
        for (int c = 0; c < COVEC; c++) acc[o * COVEC + c] = bias[co0 + c];

    const int DIN2 = Din * Din;
    const float* xn = x + (size_t)n * CIN * Din * DIN2;

    for (int ci = 0; ci < CIN; ci++) {
        const float* xc = xn + (size_t)ci * Din * DIN2;
        const float* wc = ws + ci * 64 * COVEC;
#pragma unroll
        for (int u = 0; u < 6; u++) {
            // cache the 6x6 input plane at z = zb + u
            float xp[36];
            const float* rowz = xc + (zb + u) * DIN2;
#pragma unroll
            for (int v = 0; v < 6; v++) {
#pragma unroll
                for (int t = 0; t < 6; t++) {
                    bool pv = pz[u] && py[v] && px[t];
                    xp[v * 6 + t] = pv ? __ldg(rowz + (yb + v) * Din + (xb + t)) : 0.f;
                }
            }
#pragma unroll
            for (int rd = 0; rd < 2; rd++) {
                const int a_d = u - 2 * rd;
                if (a_d < 0 || a_d > 3) continue;   // compile-time after unroll
#pragma unroll
                for (int ah = 0; ah < 4; ah++) {
#pragma unroll
                    for (int aw = 0; aw < 4; aw++) {
                        const float* wv = wc + ((a_d * 4 + ah) * 4 + aw) * COVEC;
                        float wr[COVEC];
#pragma unroll
                        for (int c = 0; c < COVEC; c++) wr[c] = wv[c];
#pragma unroll
                        for (int rh = 0; rh < 2; rh++) {
#pragma unroll
                            for (int rw = 0; rw < 2; rw++) {
                                const float xv = xp[(2 * rh + ah) * 6 + (2 * rw + aw)];
                                const int o = (rd * 2 + rh) * 2 + rw;
#pragma unroll
                                for (int c = 0; c < COVEC; c++)
                                    acc[o * COVEC + c] = fmaf(xv, wr[c], acc[o * COVEC + c]);
                            }
                        }
                    }
                }
            }
        }
    }

    const int OUT2 = Dout * Dout;
    const size_t OUT3 = (size_t)OUT2 * Dout;
    float* yo = y + ((size_t)(n * Cout + co0) * Dout + 2 * bd) * OUT2
                  + (2 * bh) * Dout + 2 * bw;
#pragma unroll
    for (int c = 0; c < COVEC; c++) {
#pragma unroll
        for (int rd = 0; rd < 2; rd++)
#pragma unroll
            for (int rh = 0; rh < 2; rh++)
#pragma unroll
                for (int rw = 0; rw < 2; rw++) {
                    float r = acc[((rd * 2 + rh) * 2 + rw) * COVEC + c];
                    if (ACT == 1) r = fmaxf(r, 0.f);
                    yo[c * OUT3 + rd * OUT2 + rh * Dout + rw] = r;
                }
    }
}

// ===========================================================================
// Transposed conv3d, k=4 s=2 p=1. One thread = one input base position b,
// producing the 2x2x2 output block (2b+r). Per dim, output r gets input
// b+delta with tap t = r + 1 - 2*delta; the map t -> (r, delta) is bijective:
//   t=0:(r=1,d=+1)  t=1:(r=0,d=0)  t=2:(r=1,d=0)  t=3:(r=0,d=-1)
// Input cube 3^3 cached in regs per ci. Weights: PyTorch [CIN][Cout][4][4][4].
// ACT: 0 none, 1 relu, 2 sigmoid
// ===========================================================================
template <int CIN, int COVEC, int ACT>
__global__ void convT_blk(const float* __restrict__ x,
                          const float* __restrict__ w,
                          const float* __restrict__ bias,
                          float* __restrict__ y,
                          int In, int Out, int Cout)
{
    extern __shared__ float ws[]; // [CIN*64][COVEC]
    const int co0 = blockIdx.y * COVEC;
    const int n   = blockIdx.z;

    const int WTOT = CIN * 64 * COVEC;
    for (int e = threadIdx.x; e < WTOT; e += blockDim.x) {
        int v  = e % COVEC;
        int r  = e / COVEC;
        int ci = r >> 6, t = r & 63;
        ws[e] = w[((size_t)ci * Cout + co0 + v) * 64 + t];
    }
    __syncthreads();

    const int pos = blockIdx.x * blockDim.x + threadIdx.x; // base index in In^3
    const int bw = pos % In;
    const int bh = (pos / In) % In;
    const int bd = pos / (In * In);

    bool pd[3], ph[3], pw[3];
    pd[0] = (bd > 0); pd[1] = true; pd[2] = (bd < In - 1);
    ph[0] = (bh > 0); ph[1] = true; ph[2] = (bh < In - 1);
    pw[0] = (bw > 0); pw[1] = true; pw[2] = (bw < In - 1);

    float acc[8 * COVEC];
#pragma unroll
    for (int o = 0; o < 8; o++)
#pragma unroll
        for (int c = 0; c < COVEC; c++) acc[o * COVEC + c] = bias[co0 + c];

    const int IN2 = In * In;
    const size_t IN3 = (size_t)IN2 * In;
    const float* xn = x + (size_t)n * CIN * IN3;

    for (int ci = 0; ci < CIN; ci++) {
        const float* xc = xn + ci * IN3;
        const float* wc = ws + ci * 64 * COVEC;

        // cache 3x3x3 input cube
        float xq[27];
#pragma unroll
        for (int dz = 0; dz < 3; dz++)
#pragma unroll
            for (int dy = 0; dy < 3; dy++)
#pragma unroll
                for (int dx = 0; dx < 3; dx++) {
                    bool pv = pd[dz] && ph[dy] && pw[dx];
                    xq[(dz * 3 + dy) * 3 + dx] =
                        pv ? __ldg(xc + (bd + dz - 1) * IN2 + (bh + dy - 1) * In + (bw + dx - 1))
                           : 0.f;
                }

#pragma unroll
        for (int td = 0; td < 4; td++) {
            const int rd = 1 - (td & 1);
            const int dz = (rd + 3 - td) >> 1;   // delta+1
#pragma unroll
            for (int th = 0; th < 4; th++) {
                const int rh = 1 - (th & 1);
                const int dy = (rh + 3 - th) >> 1;
#pragma unroll
                for (int tw = 0; tw < 4; tw++) {
                    const int rw = 1 - (tw & 1);
                    const int dx = (rw + 3 - tw) >> 1;
                    const float* wv = wc + ((td * 4 + th) * 4 + tw) * COVEC;
                    float wr[COVEC];
#pragma unroll
                    for (int c = 0; c < COVEC; c++) wr[c] = wv[c];
                    const float xv = xq[(dz * 3 + dy) * 3 + dx];
                    const int o = (rd * 2 + rh) * 2 + rw;
#pragma unroll
                    for (int c = 0; c < COVEC; c++)
                        acc[o * COVEC + c] = fmaf(xv, wr[c], acc[o * COVEC + c]);
                }
            }
        }
    }

    const int OUT2 = Out * Out;
    const size_t OUT3 = (size_t)OUT2 * Out;
    float* yo = y + ((size_t)(n * Cout + co0) * Out + 2 * bd) * OUT2
                  + (2 * bh) * Out + 2 * bw;
#pragma unroll
    for (int c = 0; c < COVEC; c++) {
#pragma unroll
        for (int rd = 0; rd < 2; rd++)
#pragma unroll
            for (int rh = 0; rh < 2; rh++)
#pragma unroll
                for (int rw = 0; rw < 2; rw++) {
                    float r = acc[((rd * 2 + rh) * 2 + rw) * COVEC + c];
                    if (ACT == 1) r = fmaxf(r, 0.f);
                    if (ACT == 2) r = 1.f / (1.f + __expf(-r));
                    yo[c * OUT3 + rd * OUT2 + rh * Out + rw] = r;
                }
    }
}

// ===========================================================================
// Vector quantization: argmin_k ||z - c_k||^2 == argmin_k (||c_k||^2 - 2 z.c_k).
// 256 threads/block; each block handles 128 positions; the 512-code scan is
// split across 2 threads per position (k in [0,256) / [256,512)).
// Half-0's range has strictly lower k, so the cross-half combine uses strict
// '<' on half-1's score -> identical tie-break to jnp.argmin (first min).
// ===========================================================================
__global__ void vq_kernel(const float* __restrict__ ze,
                          const float* __restrict__ cb,
                          float* __restrict__ quant)
{
    extern __shared__ float s[];
    float* scb   = s;                 // [512*64]
    float* snorm = scb + 512 * 64;    // [512]
    float* sbest = snorm + 512;       // [128]
    int*   sbidx = (int*)(sbest + 128); // [128]

    for (int e = threadIdx.x; e < 512 * 64; e += blockDim.x) scb[e] = cb[e];
    __syncthreads();
    for (int k = threadIdx.x; k < 512; k += blockDim.x) {
        float a = 0.f;
#pragma unroll
        for (int j = 0; j < 64; j++) { float c = scb[k * 64 + j]; a = fmaf(c, c, a); }
        snorm[k] = a;
    }
    __syncthreads();

    const int lp   = threadIdx.x & 127;
    const int half = threadIdx.x >> 7;
    const int p  = blockIdx.x * 128 + lp;   // 0..16383
    const int n  = p >> 12;
    const int sp = p & 4095;

    const float* zp = ze + (size_t)(n * 64) * 4096 + sp;
    float z[64];
#pragma unroll
    for (int j = 0; j < 64; j++) z[j] = __ldg(zp + j * 4096);

    const int k0 = half * 256;
    float best = 3.4e38f;
    int   bi   = k0;
    for (int k = k0; k < k0 + 256; k++) {
        const float4* c4 = (const float4*)(scb + k * 64);
        float d0 = 0.f, d1 = 0.f, d2 = 0.f, d3 = 0.f;
#pragma unroll
        for (int j = 0; j < 16; j++) {
            float4 cc = c4[j];
            d0 = fmaf(z[4 * j + 0], cc.x, d0);
            d1 = fmaf(z[4 * j + 1], cc.y, d1);
            d2 = fmaf(z[4 * j + 2], cc.z, d2);
            d3 = fmaf(z[4 * j + 3], cc.w, d3);
        }
        float score = snorm[k] - 2.f * ((d0 + d1) + (d2 + d3));
        if (score < best) { best = score; bi = k; }
    }

    if (half) { sbest[lp] = best; sbidx[lp] = bi; }
    __syncthreads();
    if (!half) {
        if (sbest[lp] < best) bi = sbidx[lp];  // half-1 wins only if strictly smaller
        sbidx[lp] = bi;
    }
    __syncthreads();

    const int fi = sbidx[lp];
    float* qp = quant + (size_t)(n * 64) * 4096 + sp;
#pragma unroll
    for (int j = 0; j < 32; j++) {
        int jj = half * 32 + j;
        qp[(size_t)jj * 4096] = scb[fi * 64 + jj];
    }
}

// ===========================================================================
// Launch
// ===========================================================================
extern "C" void kernel_launch(void* const* d_in, const int* in_sizes, int n_in,
                              void* d_out, int out_size)
{
    const float* x   = (const float*)d_in[0];
    const float* w1  = (const float*)d_in[1];
    const float* b1  = (const float*)d_in[2];
    const float* w2  = (const float*)d_in[3];
    const float* b2  = (const float*)d_in[4];
    const float* w3  = (const float*)d_in[5];
    const float* b3  = (const float*)d_in[6];
    const float* cb  = (const float*)d_in[7];
    const float* dw1 = (const float*)d_in[8];
    const float* db1 = (const float*)d_in[9];
    const float* dw2 = (const float*)d_in[10];
    const float* db2 = (const float*)d_in[11];
    const float* dw3 = (const float*)d_in[12];
    const float* db3 = (const float*)d_in[13];

    float* out   = (float*)d_out;
    const int XHAT_N = in_sizes[0];           // 4*1*128^3 = 8388608
    const int Z_N    = 4 * 64 * 16 * 16 * 16; // 1048576
    float* xhat  = out;
    float* quant = out + XHAT_N;
    float* ze    = out + XHAT_N + Z_N;

    float *h1, *h2;
    cudaGetSymbolAddress((void**)&h1, g_h1);
    cudaGetSymbolAddress((void**)&h2, g_h2);

    const int VQ_SMEM = (512 * 64 + 512 + 128 + 128) * 4; // 134144 B

    // opt-in to >48KB dynamic smem (idempotent)
    cudaFuncSetAttribute(convT_blk<64, 4, 1>,
                         cudaFuncAttributeMaxDynamicSharedMemorySize, 64 * 1024);
    cudaFuncSetAttribute(vq_kernel,
                         cudaFuncAttributeMaxDynamicSharedMemorySize, VQ_SMEM);

    const int T = 256;

    // enc1: 1->16, 128 -> 64, relu. base grid 32^3 = 32768
    {
        dim3 g(32768 / T, 16 / 4, 4);
        conv_s2_blk<1, 4, 1><<<g, T, 1 * 64 * 4 * 4>>>(x, w1, b1, h1, 128, 64, 16);
    }
    // enc2: 16->32, 64 -> 32, relu. base grid 16^3 = 4096
    {
        dim3 g(4096 / T, 32 / 4, 4);
        conv_s2_blk<16, 4, 1><<<g, T, 16 * 64 * 4 * 4>>>(h1, w2, b2, h2, 64, 32, 32);
    }
    // enc3: 32->64, 32 -> 16, no act -> z_e. base grid 8^3 = 512
    {
        dim3 g(512 / T, 64 / 2, 4);
        conv_s2_blk<32, 2, 0><<<g, T, 32 * 64 * 2 * 4>>>(h2, w3, b3, ze, 32, 16, 64);
    }
    // vq: z_e -> quantized
    {
        vq_kernel<<<128, 256, VQ_SMEM>>>(ze, cb, quant);
    }
    // dec1: 64->32, 16 -> 32, relu. base grid 16^3 = 4096
    {
        dim3 g(4096 / T, 32 / 4, 4);
        convT_blk<64, 4, 1><<<g, T, 64 * 64 * 4 * 4>>>(quant, dw1, db1, h2, 16, 32, 32);
    }
    // dec2: 32->16, 32 -> 64, relu. base grid 32^3 = 32768
    {
        dim3 g(32768 / T, 16 / 4, 4);
        convT_blk<32, 4, 1><<<g, T, 32 * 64 * 4 * 4>>>(h2, dw2, db2, h1, 32, 64, 16);
    }
    // dec3: 16->1, 64 -> 128, sigmoid. base grid 64^3 = 262144
    {
        dim3 g(262144 / T, 1, 4);
        convT_blk<16, 1, 2><<<g, T, 16 * 64 * 1 * 4>>>(h1, dw3, db3, xhat, 64, 128, 1);
    }
    (void)n_in; (void)out_size;
}

// round 8
// speedup vs baseline: 1.5595x; 1.1670x over previous
#include <cuda_runtime.h>
#include <math.h>

// ---------------------------------------------------------------------------
// VQ-VAE 3D forward (R7): packed f32x2 FMA (SASS FFMA2) everywhere.
//   enc: conv(1->16,k4s2p1)+relu -> conv(16->32)+relu -> conv(32->64) = z_e
//   vq : nearest codebook entry (512x64), quantized = codebook[argmin]
//   dec: convT(64->32)+relu -> convT(32->16)+relu -> convT(16->1)+sigmoid
// Output layout in d_out (float): [x_hat (4*1*128^3) | quantized | z_e]
// ---------------------------------------------------------------------------

typedef unsigned long long u64;

__device__ __forceinline__ u64 pk2(float lo, float hi) {
    u64 r; asm("mov.b64 %0, {%1, %2};" : "=l"(r) : "f"(lo), "f"(hi)); return r;
}
__device__ __forceinline__ u64 dup2(float v) { return pk2(v, v); }
__device__ __forceinline__ void fma2(u64& d, u64 a, u64 b) {
    asm("fma.rn.f32x2 %0, %1, %2, %0;" : "+l"(d) : "l"(a), "l"(b));
}
__device__ __forceinline__ void up2(u64 v, float& a, float& b) {
    asm("mov.b64 {%0, %1}, %2;" : "=f"(a), "=f"(b) : "l"(v));
}

// scratch (no allocations allowed) -- reused across stages
__device__ float g_h1[4 * 16 * 64 * 64 * 64]; // conv1 out / dec2 out (64 MB)
__device__ float g_h2[4 * 32 * 32 * 32 * 32]; // conv2 out / dec1 out (16 MB)

// ===========================================================================
// Strided conv3d, k=4 s=2 p=1. One thread = 2x2x2 output block x COVEC
// channels (COVEC even, channel-paired f32x2 accumulators). 6^3 input window,
// z-plane cached dup-packed in regs. Plane index u = 2r + a (a = tap).
// ACT: 0 none, 1 relu
// ===========================================================================
template <int CIN, int COVEC, int ACT>
__global__ void conv_s2_blk(const float* __restrict__ x,
                            const float* __restrict__ w,   // [Cout][CIN][4][4][4]
                            const float* __restrict__ bias,
                            float* __restrict__ y,
                            int Din, int Dout, int Cout)
{
    static_assert(COVEC % 2 == 0, "COVEC even");
    constexpr int CP = COVEC / 2;
    extern __shared__ float ws[]; // [CIN*64][COVEC]
    const int co0 = blockIdx.y * COVEC;
    const int n   = blockIdx.z;

    const int WTOT = CIN * 64 * COVEC;
    for (int e = threadIdx.x; e < WTOT; e += blockDim.x) {
        int v  = e % COVEC;
        int r  = e / COVEC;          // ci*64 + t
        int ci = r >> 6, t = r & 63;
        ws[e] = w[((co0 + v) * CIN + ci) * 64 + t];
    }
    __syncthreads();

    const int B   = Dout >> 1;
    const int pos = blockIdx.x * blockDim.x + threadIdx.x;
    const int bw = pos % B;
    const int bh = (pos / B) % B;
    const int bd = pos / (B * B);

    const int zb = 4 * bd - 1, yb = 4 * bh - 1, xb = 4 * bw - 1;
    bool pz[6], py[6], px[6];
#pragma unroll
    for (int u = 0; u < 6; u++) {
        pz[u] = (unsigned)(zb + u) < (unsigned)Din;
        py[u] = (unsigned)(yb + u) < (unsigned)Din;
        px[u] = (unsigned)(xb + u) < (unsigned)Din;
    }

    u64 acc[8 * CP];
#pragma unroll
    for (int o = 0; o < 8; o++)
#pragma unroll
        for (int c = 0; c < CP; c++)
            acc[o * CP + c] = pk2(bias[co0 + 2 * c], bias[co0 + 2 * c + 1]);

    const int DIN2 = Din * Din;
    const float* xn = x + (size_t)n * CIN * Din * DIN2;

    for (int ci = 0; ci < CIN; ci++) {
        const float* xc = xn + (size_t)ci * Din * DIN2;
        const float* wc = ws + ci * 64 * COVEC;
#pragma unroll
        for (int u = 0; u < 6; u++) {
            // cache the 6x6 input plane at z = zb + u, dup-packed
            u64 xp[36];
            const float* rowz = xc + (zb + u) * DIN2;
#pragma unroll
            for (int v = 0; v < 6; v++) {
#pragma unroll
                for (int t = 0; t < 6; t++) {
                    bool pv = pz[u] && py[v] && px[t];
                    float xv = pv ? __ldg(rowz + (yb + v) * Din + (xb + t)) : 0.f;
                    xp[v * 6 + t] = dup2(xv);
                }
            }
#pragma unroll
            for (int rd = 0; rd < 2; rd++) {
                const int a_d = u - 2 * rd;
                if (a_d < 0 || a_d > 3) continue;   // compile-time after unroll
#pragma unroll
                for (int ah = 0; ah < 4; ah++) {
#pragma unroll
                    for (int aw = 0; aw < 4; aw++) {
                        const u64* wv = (const u64*)(wc + ((a_d * 4 + ah) * 4 + aw) * COVEC);
                        u64 wr[CP];
#pragma unroll
                        for (int c = 0; c < CP; c++) wr[c] = wv[c];
#pragma unroll
                        for (int rh = 0; rh < 2; rh++) {
#pragma unroll
                            for (int rw = 0; rw < 2; rw++) {
                                const u64 xv = xp[(2 * rh + ah) * 6 + (2 * rw + aw)];
                                const int o = (rd * 2 + rh) * 2 + rw;
#pragma unroll
                                for (int c = 0; c < CP; c++)
                                    fma2(acc[o * CP + c], xv, wr[c]);
                            }
                        }
                    }
                }
            }
        }
    }

    const int OUT2 = Dout * Dout;
    const size_t OUT3 = (size_t)OUT2 * Dout;
    float* yo = y + ((size_t)(n * Cout + co0) * Dout + 2 * bd) * OUT2
                  + (2 * bh) * Dout + 2 * bw;
#pragma unroll
    for (int c = 0; c < CP; c++) {
#pragma unroll
        for (int rd = 0; rd < 2; rd++)
#pragma unroll
            for (int rh = 0; rh < 2; rh++)
#pragma unroll
                for (int rw = 0; rw < 2; rw++) {
                    float v0, v1;
                    up2(acc[((rd * 2 + rh) * 2 + rw) * CP + c], v0, v1);
                    if (ACT == 1) { v0 = fmaxf(v0, 0.f); v1 = fmaxf(v1, 0.f); }
                    yo[(2 * c + 0) * OUT3 + rd * OUT2 + rh * Dout + rw] = v0;
                    yo[(2 * c + 1) * OUT3 + rd * OUT2 + rh * Dout + rw] = v1;
                }
    }
}

// ===========================================================================
// Transposed conv3d, k=4 s=2 p=1 (COVEC even, channel-paired f32x2).
// One thread = one input base b -> 2x2x2 output block. tap t -> (r, delta):
//   t=0:(1,+1)  t=1:(0,0)  t=2:(1,0)  t=3:(0,-1).   3^3 input cube cached.
// Weights: PyTorch ConvTranspose layout [CIN][Cout][4][4][4].
// ACT: 0 none, 1 relu
// ===========================================================================
template <int CIN, int COVEC, int ACT>
__global__ void convT_blk(const float* __restrict__ x,
                          const float* __restrict__ w,
                          const float* __restrict__ bias,
                          float* __restrict__ y,
                          int In, int Out, int Cout)
{
    static_assert(COVEC % 2 == 0, "COVEC even");
    constexpr int CP = COVEC / 2;
    extern __shared__ float ws[]; // [CIN*64][COVEC]
    const int co0 = blockIdx.y * COVEC;
    const int n   = blockIdx.z;

    const int WTOT = CIN * 64 * COVEC;
    for (int e = threadIdx.x; e < WTOT; e += blockDim.x) {
        int v  = e % COVEC;
        int r  = e / COVEC;
        int ci = r >> 6, t = r & 63;
        ws[e] = w[((size_t)ci * Cout + co0 + v) * 64 + t];
    }
    __syncthreads();

    const int pos = blockIdx.x * blockDim.x + threadIdx.x;
    const int bw = pos % In;
    const int bh = (pos / In) % In;
    const int bd = pos / (In * In);

    bool pd[3], ph[3], pw[3];
    pd[0] = (bd > 0); pd[1] = true; pd[2] = (bd < In - 1);
    ph[0] = (bh > 0); ph[1] = true; ph[2] = (bh < In - 1);
    pw[0] = (bw > 0); pw[1] = true; pw[2] = (bw < In - 1);

    u64 acc[8 * CP];
#pragma unroll
    for (int o = 0; o < 8; o++)
#pragma unroll
        for (int c = 0; c < CP; c++)
            acc[o * CP + c] = pk2(bias[co0 + 2 * c], bias[co0 + 2 * c + 1]);

    const int IN2 = In * In;
    const size_t IN3 = (size_t)IN2 * In;
    const float* xn = x + (size_t)n * CIN * IN3;

    for (int ci = 0; ci < CIN; ci++) {
        const float* xc = xn + ci * IN3;
        const float* wc = ws + ci * 64 * COVEC;

        u64 xq[27]; // dup-packed 3x3x3 cube
#pragma unroll
        for (int dz = 0; dz < 3; dz++)
#pragma unroll
            for (int dy = 0; dy < 3; dy++)
#pragma unroll
                for (int dx = 0; dx < 3; dx++) {
                    bool pv = pd[dz] && ph[dy] && pw[dx];
                    float xv = pv ? __ldg(xc + (bd + dz - 1) * IN2 + (bh + dy - 1) * In + (bw + dx - 1))
                                  : 0.f;
                    xq[(dz * 3 + dy) * 3 + dx] = dup2(xv);
                }

#pragma unroll
        for (int td = 0; td < 4; td++) {
            const int rd = 1 - (td & 1);
            const int dz = (rd + 3 - td) >> 1;   // delta+1
#pragma unroll
            for (int th = 0; th < 4; th++) {
                const int rh = 1 - (th & 1);
                const int dy = (rh + 3 - th) >> 1;
#pragma unroll
                for (int tw = 0; tw < 4; tw++) {
                    const int rw = 1 - (tw & 1);
                    const int dx = (rw + 3 - tw) >> 1;
                    const u64* wv = (const u64*)(wc + ((td * 4 + th) * 4 + tw) * COVEC);
                    const u64 xv = xq[(dz * 3 + dy) * 3 + dx];
                    const int o = (rd * 2 + rh) * 2 + rw;
#pragma unroll
                    for (int c = 0; c < CP; c++)
                        fma2(acc[o * CP + c], xv, wv[c]);
                }
            }
        }
    }

    const int OUT2 = Out * Out;
    const size_t OUT3 = (size_t)OUT2 * Out;
    float* yo = y + ((size_t)(n * Cout + co0) * Out + 2 * bd) * OUT2
                  + (2 * bh) * Out + 2 * bw;
#pragma unroll
    for (int c = 0; c < CP; c++) {
#pragma unroll
        for (int rd = 0; rd < 2; rd++)
#pragma unroll
            for (int rh = 0; rh < 2; rh++)
#pragma unroll
                for (int rw = 0; rw < 2; rw++) {
                    float v0, v1;
                    up2(acc[((rd * 2 + rh) * 2 + rw) * CP + c], v0, v1);
                    if (ACT == 1) { v0 = fmaxf(v0, 0.f); v1 = fmaxf(v1, 0.f); }
                    yo[(2 * c + 0) * OUT3 + rd * OUT2 + rh * Out + rw] = v0;
                    yo[(2 * c + 1) * OUT3 + rd * OUT2 + rh * Out + rw] = v1;
                }
    }
}

// ===========================================================================
// dec3 special: transposed conv, CIN=16 -> Cout=1, sigmoid. One thread =
// TWO adjacent w input-bases (3x3x4 cube) -> 2x2x4 outputs; w-output pair
// (rw0, rw1) packed in one f32x2 accumulator:
//   acc(rw0,rw1) += dup(x[beta+1])        * (w[tw=1], w[tw=2])
//                +  (x[beta], x[beta+2])  * (w[tw=3], w[tw=0])
// Packed weight table (512 u64) prebuilt in smem. Output stored as float4.
// ===========================================================================
__global__ void convT_c1_sig(const float* __restrict__ x,
                             const float* __restrict__ w,   // [16][1][4][4][4]
                             const float* __restrict__ bias,
                             float* __restrict__ y,
                             int In, int Out)
{
    constexpr int CIN = 16;
    extern __shared__ float smf[];
    u64* ws2 = (u64*)smf; // [CIN][16 (td*4+th)][2]
    const int n = blockIdx.z;

    for (int e = threadIdx.x; e < CIN * 16 * 2; e += blockDim.x) {
        int pr = e & 1;
        int tt = (e >> 1) & 15;      // td*4+th
        int ci = e >> 5;
        const float* wb = w + ci * 64 + tt * 4; // [tw]
        ws2[e] = pr ? pk2(wb[3], wb[0]) : pk2(wb[1], wb[2]);
    }
    __syncthreads();

    const int BQ = In >> 1; // w base-pairs per dim
    const int pos = blockIdx.x * blockDim.x + threadIdx.x;
    const int bq = pos % BQ;
    const int bh = (pos / BQ) % In;
    const int bd = pos / (BQ * In);
    const int bw0 = 2 * bq;

    bool pd[3], ph[3], pw4[4];
    pd[0] = (bd > 0); pd[1] = true; pd[2] = (bd < In - 1);
    ph[0] = (bh > 0); ph[1] = true; ph[2] = (bh < In - 1);
    pw4[0] = (bw0 > 0); pw4[1] = true; pw4[2] = true; pw4[3] = (bw0 + 2 < In);

    const float bv = __ldg(bias);
    u64 acc[8]; // [(rd*2+rh)*2 + beta], each packs (rw0, rw1)
#pragma unroll
    for (int o = 0; o < 8; o++) acc[o] = dup2(bv);

    // tap/source maps per dim: (r, s) -> tap, cube-index
    const int TD[2][2] = {{1, 3}, {0, 2}};
    const int DZ[2][2] = {{1, 0}, {2, 1}};

    const int IN2 = In * In;
    const size_t IN3 = (size_t)IN2 * In;
    const float* xn = x + (size_t)n * CIN * IN3;

    for (int ci = 0; ci < CIN; ci++) {
        const float* xc = xn + ci * IN3;
        const u64* wt = ws2 + ci * 32;

        u64 xd[9][2], xcr[9][2]; // dup / cross packs per (dz,dy)
#pragma unroll
        for (int dz = 0; dz < 3; dz++)
#pragma unroll
            for (int dy = 0; dy < 3; dy++) {
                const float* row = xc + (bd + dz - 1) * IN2 + (bh + dy - 1) * In + (bw0 - 1);
                const bool pr = pd[dz] && ph[dy];
                float xv[4];
#pragma unroll
                for (int t = 0; t < 4; t++)
                    xv[t] = (pr && pw4[t]) ? __ldg(row + t) : 0.f;
                const int e = dz * 3 + dy;
                xd[e][0]  = dup2(xv[1]);
                xd[e][1]  = dup2(xv[2]);
                xcr[e][0] = pk2(xv[0], xv[2]);
                xcr[e][1] = pk2(xv[1], xv[3]);
            }

#pragma unroll
        for (int rd = 0; rd < 2; rd++)
#pragma unroll
            for (int sd = 0; sd < 2; sd++) {
                const int td = TD[rd][sd], dz = DZ[rd][sd];
#pragma unroll
                for (int rh = 0; rh < 2; rh++)
#pragma unroll
                    for (int sh = 0; sh < 2; sh++) {
                        const int th = TD[rh][sh], dy = DZ[rh][sh];
                        const u64 pA = wt[(td * 4 + th) * 2 + 0];
                        const u64 pB = wt[(td * 4 + th) * 2 + 1];
                        const int e = dz * 3 + dy;
#pragma unroll
                        for (int be = 0; be < 2; be++) {
                            const int o = (rd * 2 + rh) * 2 + be;
                            fma2(acc[o], xd[e][be], pA);
                            fma2(acc[o], xcr[e][be], pB);
                        }
                    }
            }
    }

    const int OUT2 = Out * Out;
    float* yo = y + ((size_t)n * Out + 2 * bd) * OUT2 + (2 * bh) * Out + 4 * bq;
#pragma unroll
    for (int rd = 0; rd < 2; rd++)
#pragma unroll
        for (int rh = 0; rh < 2; rh++) {
            float4 r;
            float a, b;
            up2(acc[(rd * 2 + rh) * 2 + 0], a, b);
            r.x = 1.f / (1.f + __expf(-a));
            r.y = 1.f / (1.f + __expf(-b));
            up2(acc[(rd * 2 + rh) * 2 + 1], a, b);
            r.z = 1.f / (1.f + __expf(-a));
            r.w = 1.f / (1.f + __expf(-b));
            *(float4*)(yo + rd * OUT2 + rh * Out) = r;
        }
}

// ===========================================================================
// Vector quantization: argmin_k (||c_k||^2 - 2 z.c_k), f32x2 dot products.
// 512 threads/block, 128 positions/block; the 512-code scan is split across
// 4 threads per position (quarters of 128 codes). Lower quarter = lower k,
// so the combine uses strict '<' in ascending-quarter order -> identical
// tie-break to jnp.argmin (first minimum).
// ===========================================================================
__global__ void vq_kernel(const float* __restrict__ ze,
                          const float* __restrict__ cb,
                          float* __restrict__ quant)
{
    extern __shared__ float s[];
    float* scb   = s;                   // [512*64]
    float* snorm = scb + 512 * 64;      // [512]
    float* sbest = snorm + 512;         // [4][128]
    int*   sbidx = (int*)(sbest + 512); // [4][128]

    for (int e = threadIdx.x; e < 512 * 64; e += blockDim.x) scb[e] = cb[e];
    __syncthreads();
    for (int k = threadIdx.x; k < 512; k += blockDim.x) {
        float a = 0.f;
#pragma unroll
        for (int j = 0; j < 64; j++) { float c = scb[k * 64 + j]; a = fmaf(c, c, a); }
        snorm[k] = a;
    }
    __syncthreads();

    const int lp = threadIdx.x & 127;
    const int q  = threadIdx.x >> 7;        // quarter 0..3
    const int p  = blockIdx.x * 128 + lp;   // 0..16383
    const int n  = p >> 12;
    const int sp = p & 4095;

    const float* zp = ze + (size_t)(n * 64) * 4096 + sp;
    u64 z2[32];
#pragma unroll
    for (int j = 0; j < 32; j++)
        z2[j] = pk2(__ldg(zp + (2 * j) * 4096), __ldg(zp + (2 * j + 1) * 4096));

    const int k0 = q * 128;
    float best = 3.4e38f;
    int   bi   = k0;
    for (int k = k0; k < k0 + 128; k++) {
        const ulonglong2* c2 = (const ulonglong2*)(scb + k * 64);
        u64 a0 = 0ull, a1 = 0ull; // (0.f, 0.f)
#pragma unroll
        for (int j = 0; j < 16; j++) {
            ulonglong2 cc = c2[j];
            fma2(a0, z2[2 * j + 0], cc.x);
            fma2(a1, z2[2 * j + 1], cc.y);
        }
        float s0, s1, s2, s3;
        up2(a0, s0, s1); up2(a1, s2, s3);
        float score = snorm[k] - 2.f * ((s0 + s1) + (s2 + s3));
        if (score < best) { best = score; bi = k; }
    }

    sbest[q * 128 + lp] = best;
    sbidx[q * 128 + lp] = bi;
    __syncthreads();
    if (q == 0) {
#pragma unroll
        for (int qq = 1; qq < 4; qq++) {
            float ob = sbest[qq * 128 + lp];
            if (ob < best) { best = ob; bi = sbidx[qq * 128 + lp]; }
        }
        sbidx[lp] = bi;
    }
    __syncthreads();

    const int fi = sbidx[lp];
    float* qp = quant + (size_t)(n * 64) * 4096 + sp;
#pragma unroll
    for (int j = 0; j < 16; j++) {
        int jj = q * 16 + j;
        qp[(size_t)jj * 4096] = scb[fi * 64 + jj];
    }
}

// ===========================================================================
// Launch
// ===========================================================================
extern "C" void kernel_launch(void* const* d_in, const int* in_sizes, int n_in,
                              void* d_out, int out_size)
{
    const float* x   = (const float*)d_in[0];
    const float* w1  = (const float*)d_in[1];
    const float* b1  = (const float*)d_in[2];
    const float* w2  = (const float*)d_in[3];
    const float* b2  = (const float*)d_in[4];
    const float* w3  = (const float*)d_in[5];
    const float* b3  = (const float*)d_in[6];
    const float* cb  = (const float*)d_in[7];
    const float* dw1 = (const float*)d_in[8];
    const float* db1 = (const float*)d_in[9];
    const float* dw2 = (const float*)d_in[10];
    const float* db2 = (const float*)d_in[11];
    const float* dw3 = (const float*)d_in[12];
    const float* db3 = (const float*)d_in[13];

    float* out   = (float*)d_out;
    const int XHAT_N = in_sizes[0];           // 4*1*128^3 = 8388608
    const int Z_N    = 4 * 64 * 16 * 16 * 16; // 1048576
    float* xhat  = out;
    float* quant = out + XHAT_N;
    float* ze    = out + XHAT_N + Z_N;

    float *h1, *h2;
    cudaGetSymbolAddress((void**)&h1, g_h1);
    cudaGetSymbolAddress((void**)&h2, g_h2);

    const int VQ_SMEM = (512 * 64 + 512 + 512 + 512) * 4; // 137216 B

    // opt-in to >48KB dynamic smem (idempotent)
    cudaFuncSetAttribute(convT_blk<64, 4, 1>,
                         cudaFuncAttributeMaxDynamicSharedMemorySize, 64 * 1024);
    cudaFuncSetAttribute(vq_kernel,
                         cudaFuncAttributeMaxDynamicSharedMemorySize, VQ_SMEM);

    const int T = 256;

    // enc1: 1->16, 128 -> 64, relu. base grid 32^3 = 32768
    {
        dim3 g(32768 / T, 16 / 4, 4);
        conv_s2_blk<1, 4, 1><<<g, T, 1 * 64 * 4 * 4>>>(x, w1, b1, h1, 128, 64, 16);
    }
    // enc2: 16->32, 64 -> 32, relu. base grid 16^3 = 4096
    {
        dim3 g(4096 / T, 32 / 4, 4);
        conv_s2_blk<16, 4, 1><<<g, T, 16 * 64 * 4 * 4>>>(h1, w2, b2, h2, 64, 32, 32);
    }
    // enc3: 32->64, 32 -> 16, no act -> z_e. base grid 8^3 = 512
    {
        dim3 g(512 / T, 64 / 2, 4);
        conv_s2_blk<32, 2, 0><<<g, T, 32 * 64 * 2 * 4>>>(h2, w3, b3, ze, 32, 16, 64);
    }
    // vq: z_e -> quantized
    {
        vq_kernel<<<128, 512, VQ_SMEM>>>(ze, cb, quant);
    }
    // dec1: 64->32, 16 -> 32, relu. base grid 16^3 = 4096
    {
        dim3 g(4096 / T, 32 / 4, 4);
        convT_blk<64, 4, 1><<<g, T, 64 * 64 * 4 * 4>>>(quant, dw1, db1, h2, 16, 32, 32);
    }
    // dec2: 32->16, 32 -> 64, relu. base grid 32^3 = 32768
    {
        dim3 g(32768 / T, 16 / 4, 4);
        convT_blk<32, 4, 1><<<g, T, 32 * 64 * 4 * 4>>>(h2, dw2, db2, h1, 32, 64, 16);
    }
    // dec3: 16->1, 64 -> 128, sigmoid. base-pair grid 64*64*32 = 131072
    {
        dim3 g(131072 / T, 1, 4);
        convT_c1_sig<<<g, T, 16 * 16 * 2 * 8>>>(h1, dw3, db3, xhat, 64, 128);
    }
    (void)n_in; (void)out_size;
}